// round 1
// baseline (speedup 1.0000x reference)
#include <cuda_runtime.h>
#include <cuda_bf16.h>
#include <math.h>

// Problem constants
#define BB 1024
#define SS 200
#define II 4
#define HH 128
#define JH (II*HH)          // 512
#define SH (SS*HH)          // 25600  (item_eb row stride per b)
#define WS (JH*HH)          // 65536  (w stride per s)
#define HAT_ELEMS (1ll*BB*II*SS*HH)   // 104,857,600 floats = 419 MB

// Scratch for hat in [B][I][S][H] layout (device-global: allocation-free per rules)
__device__ float g_hat[BB * II * SS * HH];

// ---------------------------------------------------------------------------
// Phase 1: hat[b,i,s,h] = sum_k item[b,s,k] * w[s, i*128+h, k]
// Per block: one s, one i (128 j-cols), one 128-row b-tile.
// SMEM: As[128][129], Ws[128][129] (pitch 129 kills frag-load conflicts).
// 256 threads, each computes an 8x8 microtile.
// ---------------------------------------------------------------------------
__global__ __launch_bounds__(256, 1)
void gemm_hat_kernel(const float* __restrict__ item, const float* __restrict__ w)
{
    extern __shared__ float sm[];
    float* As = sm;               // [128][129]
    float* Ws = sm + 128 * 129;   // [128][129]

    const int s     = blockIdx.y;
    const int cap_i = blockIdx.z;
    const int b0    = blockIdx.x << 7;
    const int tid   = threadIdx.x;

    const float* ga = item + (size_t)b0 * SH + (size_t)s * HH;
    const float* gw = w + (size_t)s * WS + (size_t)cap_i * HH * HH;

    // Load both 128x128 tiles (float4 global, scalar smem stores for pitch 129)
    #pragma unroll
    for (int q = 0; q < 16; q++) {
        int idx = q * 256 + tid;
        int row = idx >> 5;
        int k4  = (idx & 31) << 2;
        float4 av = *(const float4*)(ga + (size_t)row * SH + k4);
        float4 wv = *(const float4*)(gw + row * HH + k4);
        float* pa = As + row * 129 + k4;
        pa[0] = av.x; pa[1] = av.y; pa[2] = av.z; pa[3] = av.w;
        float* pw = Ws + row * 129 + k4;
        pw[0] = wv.x; pw[1] = wv.y; pw[2] = wv.z; pw[3] = wv.w;
    }
    __syncthreads();

    // Warp grid 2(m) x 4(n); lane grid 8(m) x 4(n); thread tile 8x8.
    const int wid  = tid >> 5;
    const int lane = tid & 31;
    const int wm = wid & 1, wn = wid >> 1;
    const int lm = lane & 7, ln = lane >> 3;
    const int m0 = wm * 64 + lm * 8;
    const int n0 = wn * 32 + ln * 8;

    float acc[8][8];
    #pragma unroll
    for (int r = 0; r < 8; r++)
        #pragma unroll
        for (int c = 0; c < 8; c++) acc[r][c] = 0.f;

    #pragma unroll 4
    for (int k = 0; k < 128; k++) {
        float a[8], b[8];
        #pragma unroll
        for (int r = 0; r < 8; r++) a[r] = As[(m0 + r) * 129 + k];
        #pragma unroll
        for (int c = 0; c < 8; c++) b[c] = Ws[(n0 + c) * 129 + k];
        #pragma unroll
        for (int r = 0; r < 8; r++)
            #pragma unroll
            for (int c = 0; c < 8; c++)
                acc[r][c] = fmaf(a[r], b[c], acc[r][c]);
    }

    // Write to g_hat[b][i][s][h]
    #pragma unroll
    for (int r = 0; r < 8; r++) {
        size_t base = ((size_t)(b0 + m0 + r) * II + cap_i) * (size_t)SH
                    + (size_t)s * HH + n0;
        float4 v0 = make_float4(acc[r][0], acc[r][1], acc[r][2], acc[r][3]);
        float4 v1 = make_float4(acc[r][4], acc[r][5], acc[r][6], acc[r][7]);
        *(float4*)(g_hat + base)     = v0;
        *(float4*)(g_hat + base + 4) = v1;
    }
}

// ---------------------------------------------------------------------------
// Phase 2: dynamic routing. One block per (b,i). hat[b,i] (100 KB) staged in
// SMEM once; all 3 routing iterations run from SMEM.
// ---------------------------------------------------------------------------
__device__ __forceinline__ float warp_sum(float v) {
    #pragma unroll
    for (int o = 16; o > 0; o >>= 1) v += __shfl_xor_sync(0xffffffffu, v, o);
    return v;
}
__device__ __forceinline__ float warp_max(float v) {
    #pragma unroll
    for (int o = 16; o > 0; o >>= 1) v = fmaxf(v, __shfl_xor_sync(0xffffffffu, v, o));
    return v;
}

__global__ __launch_bounds__(256, 2)
void routing_kernel(const int* __restrict__ mask, float* __restrict__ out)
{
    extern __shared__ float sm[];
    float* hs   = sm;               // [200][128] hat tile
    float* cw   = sm + SS * HH;     // [200] capsule_weight
    float* swt  = cw + SS;          // [200] softmax weights (masked)
    float* capp = swt + SS;         // [256] cap partials
    float* cap  = capp + 256;       // [128] squashed capsule
    float* red  = cap + 128;        // [16]  reduction scratch
    int*   msk  = (int*)(red + 16); // [200]

    const int tid  = threadIdx.x;
    const int b    = blockIdx.x >> 2;
    const int lane = tid & 31;
    const int wid  = tid >> 5;

    // Stage hat[b,i] (6400 float4)
    const float4* src = (const float4*)(g_hat + (size_t)blockIdx.x * SH);
    float4* dst = (float4*)hs;
    #pragma unroll
    for (int q = 0; q < 25; q++) {
        int idx = q * 256 + tid;
        dst[idx] = src[idx];
    }
    if (tid < SS) {
        msk[tid] = mask[b * SS + tid];
        cw[tid]  = 0.f;
    }
    __syncthreads();

    const float NEG_INF = __int_as_float(0xff800000);

    for (int it = 0; it < 3; it++) {
        // ---- softmax over s (all 200, mask applied AFTER normalization) ----
        float v = (tid < SS) ? cw[tid] : NEG_INF;
        float wm_ = warp_max(v);
        if (lane == 0) red[wid] = wm_;
        __syncthreads();
        float bm = red[0];
        #pragma unroll
        for (int j = 1; j < 8; j++) bm = fmaxf(bm, red[j]);
        float e = (tid < SS) ? expf(v - bm) : 0.f;
        float wsum = warp_sum(e);
        __syncthreads();                  // all have read red[] (max)
        if (lane == 0) red[wid] = wsum;
        __syncthreads();
        float Z = 0.f;
        #pragma unroll
        for (int j = 0; j < 8; j++) Z += red[j];
        if (tid < SS) swt[tid] = msk[tid] ? (e / Z) : 0.f;
        __syncthreads();

        // ---- cap[h] = sum_s sw[s] * hat[s][h] (two s-halves per h) ----
        {
            int h    = tid & 127;
            int half = tid >> 7;
            int s0   = half * 100;
            float c = 0.f;
            #pragma unroll 4
            for (int s = s0; s < s0 + 100; s++)
                c = fmaf(swt[s], hs[s * HH + h], c);
            capp[tid] = c;
        }
        __syncthreads();

        // ---- squash ----
        float cv = 0.f, np = 0.f;
        if (tid < 128) {
            cv = capp[tid] + capp[tid + 128];
            np = cv * cv;
        }
        float wn = warp_sum(np);
        __syncthreads();                  // red[] (Z) fully consumed
        if (lane == 0) red[wid] = wn;
        __syncthreads();
        float n = 0.f;
        #pragma unroll
        for (int j = 0; j < 8; j++) n += red[j];
        float factor = n / (1.f + n) * rsqrtf(n + 1e-9f);
        if (tid < 128) cap[tid] = cv * factor;
        __syncthreads();

        // ---- delta: cw[s] += hat[s,:] . cap (NOT masked) ----
        if (it < 2) {
            for (int s = wid; s < SS; s += 8) {
                const float* hr = hs + s * HH;
                float d = hr[lane]      * cap[lane]
                        + hr[lane + 32] * cap[lane + 32]
                        + hr[lane + 64] * cap[lane + 64]
                        + hr[lane + 96] * cap[lane + 96];
                d = warp_sum(d);
                if (lane == 0) cw[s] += d;
            }
            __syncthreads();
        }
    }

    if (tid < 128)
        out[(size_t)blockIdx.x * HH + tid] = cap[tid];
}

// ---------------------------------------------------------------------------
extern "C" void kernel_launch(void* const* d_in, const int* in_sizes, int n_in,
                              void* d_out, int out_size)
{
    const float* item = (const float*)d_in[0];
    const int*   mask = (const int*)d_in[1];
    const float* w    = (const float*)d_in[2];
    float*       out  = (float*)d_out;

    const int smem_gemm  = 2 * 128 * 129 * (int)sizeof(float);          // 132096
    const int smem_route = (SS * HH + SS + SS + 256 + 128 + 16) * (int)sizeof(float)
                         + SS * (int)sizeof(int);                        // ~106 KB

    cudaFuncSetAttribute(gemm_hat_kernel,
                         cudaFuncAttributeMaxDynamicSharedMemorySize, smem_gemm);
    cudaFuncSetAttribute(routing_kernel,
                         cudaFuncAttributeMaxDynamicSharedMemorySize, smem_route);

    dim3 ggrid(BB / 128, SS, II);   // (8, 200, 4)
    gemm_hat_kernel<<<ggrid, 256, smem_gemm>>>(item, w);

    routing_kernel<<<BB * II, 256, smem_route>>>(mask, out);
}

// round 3
// speedup vs baseline: 1.9718x; 1.9718x over previous
#include <cuda_runtime.h>
#include <cuda_bf16.h>
#include <math.h>
#include <stdint.h>

#define BB 1024
#define SS 200
#define II 4
#define HH 128
#define SH (SS*HH)          // 25600
#define WS (II*HH*HH)       // 65536

__device__ float g_hat[(size_t)BB * II * SS * HH];   // [b][i][s][h], 419 MB

// ---------------------------------------------------------------------------
// warp-level tensor-core helpers (plain sm_103-legal: ldmatrix + mma.sync)
// ---------------------------------------------------------------------------
__device__ __forceinline__ uint32_t smem_u32(const void* p) {
    uint32_t a;
    asm("{ .reg .u64 t; cvta.to.shared.u64 t, %1; cvt.u32.u64 %0, t; }"
        : "=r"(a) : "l"(p));
    return a;
}
__device__ __forceinline__ void ldm4(uint32_t* r, uint32_t addr) {
    asm volatile("ldmatrix.sync.aligned.m8n8.x4.shared.b16 {%0,%1,%2,%3}, [%4];"
        : "=r"(r[0]), "=r"(r[1]), "=r"(r[2]), "=r"(r[3]) : "r"(addr));
}
__device__ __forceinline__ void mma16816(float* c, const uint32_t* a, const uint32_t* b) {
    asm volatile(
        "mma.sync.aligned.m16n8k16.row.col.f32.bf16.bf16.f32 "
        "{%0,%1,%2,%3}, {%4,%5,%6,%7}, {%8,%9}, {%0,%1,%2,%3};"
        : "+f"(c[0]), "+f"(c[1]), "+f"(c[2]), "+f"(c[3])
        : "r"(a[0]), "r"(a[1]), "r"(a[2]), "r"(a[3]), "r"(b[0]), "r"(b[1]));
}

// ---------------------------------------------------------------------------
// Phase 1: bf16-split HMMA GEMM. Block = (btile, cap_i, s): M=N=K=128.
// smem tiles: pitch 136 bf16 (272 B) -> rows shift by 16B, ldmatrix conflict-free.
// ---------------------------------------------------------------------------
#define PITCH 136
#define TILEB (128 * PITCH * 2)   // 34816 B
#define A_HI 0
#define A_LO (TILEB)
#define B_HI (2*TILEB)
#define B_LO (3*TILEB)
#define SMEM_GEMM (4*TILEB)       // 139264 B

__device__ __forceinline__ uint32_t pack2(__nv_bfloat16 a, __nv_bfloat16 b) {
    __nv_bfloat162 t; t.x = a; t.y = b;
    return *(uint32_t*)&t;
}
__device__ __forceinline__ void split_store(char* hi, char* lo, int row, int k, float4 v) {
    __nv_bfloat16 h0 = __float2bfloat16(v.x), h1 = __float2bfloat16(v.y);
    __nv_bfloat16 h2 = __float2bfloat16(v.z), h3 = __float2bfloat16(v.w);
    __nv_bfloat16 l0 = __float2bfloat16(v.x - __bfloat162float(h0));
    __nv_bfloat16 l1 = __float2bfloat16(v.y - __bfloat162float(h1));
    __nv_bfloat16 l2 = __float2bfloat16(v.z - __bfloat162float(h2));
    __nv_bfloat16 l3 = __float2bfloat16(v.w - __bfloat162float(h3));
    uint32_t off = (uint32_t)row * (PITCH*2) + (uint32_t)k * 2;   // 8B aligned (k%4==0)
    *(uint2*)(hi + off) = make_uint2(pack2(h0, h1), pack2(h2, h3));
    *(uint2*)(lo + off) = make_uint2(pack2(l0, l1), pack2(l2, l3));
}

__global__ __launch_bounds__(256, 1)
void gemm_hat_mma(const float* __restrict__ item, const float* __restrict__ w)
{
    extern __shared__ __align__(16) char smp[];
    const uint32_t sbase = smem_u32(smp);

    const int tid   = threadIdx.x;
    const int wid   = tid >> 5;
    const int lane  = tid & 31;
    const int btile = blockIdx.x >> 2;
    const int cap_i = blockIdx.x & 3;
    const int s     = blockIdx.y;
    const int b0    = btile << 7;

    // ---- load f32 tiles, split-convert to bf16 hi/lo in smem ----
    const float* ga = item + (size_t)b0 * SH + (size_t)s * HH;
    const float* gw = w + (size_t)s * WS + (size_t)(cap_i * HH) * HH;
    #pragma unroll
    for (int q = 0; q < 16; q++) {
        int idx = q * 256 + tid;
        int row = idx >> 5;
        int k4  = (idx & 31) << 2;
        float4 av = *(const float4*)(ga + (size_t)row * SH + k4);
        float4 wv = *(const float4*)(gw + row * HH + k4);
        split_store(smp + A_HI, smp + A_LO, row, k4, av);
        split_store(smp + B_HI, smp + B_LO, row, k4, wv);
    }
    __syncthreads();

    const int mw = (wid & 3) * 32;   // warp M base
    const int nw = (wid >> 2) * 64;  // warp N base

    float acc[2][8][4];
    #pragma unroll
    for (int mt = 0; mt < 2; mt++)
        #pragma unroll
        for (int nt = 0; nt < 8; nt++)
            #pragma unroll
            for (int c = 0; c < 4; c++) acc[mt][nt][c] = 0.f;

    #pragma unroll
    for (int ks = 0; ks < 8; ks++) {
        const int k0 = ks * 16;

        // A fragments: rows mw+mt*16+(lane&15), col k0 + 8*(lane>>4)
        uint32_t ah[2][4], al[2][4];
        {
            uint32_t aoff = (uint32_t)(mw + (lane & 15)) * (PITCH*2)
                          + (uint32_t)(k0 + ((lane >> 4) << 3)) * 2;
            ldm4(ah[0], sbase + A_HI + aoff);
            ldm4(ah[1], sbase + A_HI + aoff + 16 * (PITCH*2));
            ldm4(al[0], sbase + A_LO + aoff);
            ldm4(al[1], sbase + A_LO + aoff + 16 * (PITCH*2));
        }
        // B fragments: x4 covers 2 n-tiles: rows nw+p*16+8*(lane>>4)+(lane&7),
        // col k0 + 8*((lane>>3)&1)
        uint32_t bh[4][4], bl[4][4];
        {
            uint32_t boff = (uint32_t)(nw + ((lane >> 4) << 3) + (lane & 7)) * (PITCH*2)
                          + (uint32_t)(k0 + (((lane >> 3) & 1) << 3)) * 2;
            #pragma unroll
            for (int p = 0; p < 4; p++) {
                ldm4(bh[p], sbase + B_HI + boff + (uint32_t)p * 16 * (PITCH*2));
                ldm4(bl[p], sbase + B_LO + boff + (uint32_t)p * 16 * (PITCH*2));
            }
        }
        #pragma unroll
        for (int mt = 0; mt < 2; mt++)
            #pragma unroll
            for (int nt = 0; nt < 8; nt++) {
                const uint32_t* bhp = &bh[nt >> 1][(nt & 1) * 2];
                const uint32_t* blp = &bl[nt >> 1][(nt & 1) * 2];
                mma16816(acc[mt][nt], ah[mt], bhp);   // hi*hi
                mma16816(acc[mt][nt], ah[mt], blp);   // hi*lo
                mma16816(acc[mt][nt], al[mt], bhp);   // lo*hi
            }
    }

    // ---- epilogue: direct float2 stores (32B sector-aligned per g-row) ----
    const int g = lane >> 2, t = lane & 3;
    #pragma unroll
    for (int mt = 0; mt < 2; mt++) {
        int rowm = mw + mt * 16 + g;
        size_t p0 = ((size_t)(b0 + rowm) * II + cap_i) * SH + (size_t)s * HH + nw;
        size_t p1 = p0 + (size_t)8 * II * SH;   // rows g+8
        #pragma unroll
        for (int nt = 0; nt < 8; nt++) {
            *(float2*)(g_hat + p0 + nt * 8 + 2 * t) =
                make_float2(acc[mt][nt][0], acc[mt][nt][1]);
            *(float2*)(g_hat + p1 + nt * 8 + 2 * t) =
                make_float2(acc[mt][nt][2], acc[mt][nt][3]);
        }
    }
}

// ---------------------------------------------------------------------------
// Phase 2: routing, 512 threads, float4-vectorized, hat[b,i] in smem
// ---------------------------------------------------------------------------
__device__ __forceinline__ float warp_sum(float v) {
    #pragma unroll
    for (int o = 16; o > 0; o >>= 1) v += __shfl_xor_sync(0xffffffffu, v, o);
    return v;
}
__device__ __forceinline__ float warp_max(float v) {
    #pragma unroll
    for (int o = 16; o > 0; o >>= 1) v = fmaxf(v, __shfl_xor_sync(0xffffffffu, v, o));
    return v;
}

#define R_HS   0
#define R_CAPP (SS*HH)              // 25600 floats
#define R_CW   (R_CAPP + 16*128)    // +2048
#define R_SWT  (R_CW + SS)
#define R_CAP  (R_SWT + SS + 8)
#define R_RED  (R_CAP + 128)
#define SMEM_ROUTE ((R_RED + 16) * 4)

__global__ __launch_bounds__(512, 2)
void routing_kernel(const int* __restrict__ mask, float* __restrict__ out)
{
    extern __shared__ __align__(16) float sm[];
    float4* hs4   = (float4*)(sm + R_HS);
    float4* capp4 = (float4*)(sm + R_CAPP);
    float*  cw    = sm + R_CW;
    float*  swt   = sm + R_SWT;
    float4* cap4  = (float4*)(sm + R_CAP);
    float*  capf  = sm + R_CAP;
    float*  red   = sm + R_RED;

    const int tid  = threadIdx.x;
    const int lane = tid & 31;
    const int wid  = tid >> 5;
    const int b    = blockIdx.x >> 2;

    {
        const float4* src = (const float4*)(g_hat + (size_t)blockIdx.x * SH);
        for (int idx = tid; idx < SS * HH / 4; idx += 512)
            hs4[idx] = src[idx];
    }
    int my_mask = (tid < SS) ? mask[b * SS + tid] : 0;
    if (tid < SS) cw[tid] = 0.f;
    __syncthreads();

    const float NEG_INF = __int_as_float(0xff800000);

    for (int it = 0; it < 3; it++) {
        // softmax over all s (mask applied after normalization)
        float v = (tid < SS) ? cw[tid] : NEG_INF;
        float wm_ = warp_max(v);
        if (lane == 0) red[wid] = wm_;
        __syncthreads();
        float bm = red[0];
        #pragma unroll
        for (int j = 1; j < 16; j++) bm = fmaxf(bm, red[j]);
        float e = (tid < SS) ? expf(v - bm) : 0.f;
        float ws = warp_sum(e);
        __syncthreads();
        if (lane == 0) red[wid] = ws;
        __syncthreads();
        float Z = 0.f;
        #pragma unroll
        for (int j = 0; j < 16; j++) Z += red[j];
        if (tid < SS) swt[tid] = my_mask ? (e / Z) : 0.f;
        __syncthreads();

        // cap = sum_s sw[s] * hat[s,:]
        {
            int g = tid & 31, sl = tid >> 5;
            float4 acc = make_float4(0.f, 0.f, 0.f, 0.f);
            for (int s2 = sl; s2 < SS; s2 += 16) {
                float sv = swt[s2];
                float4 hv = hs4[s2 * 32 + g];
                acc.x = fmaf(sv, hv.x, acc.x);
                acc.y = fmaf(sv, hv.y, acc.y);
                acc.z = fmaf(sv, hv.z, acc.z);
                acc.w = fmaf(sv, hv.w, acc.w);
            }
            capp4[sl * 32 + g] = acc;
        }
        __syncthreads();

        // reduce + squash (warp 0)
        if (tid < 32) {
            float4 r = make_float4(0.f, 0.f, 0.f, 0.f);
            #pragma unroll
            for (int sl = 0; sl < 16; sl++) {
                float4 tv = capp4[sl * 32 + tid];
                r.x += tv.x; r.y += tv.y; r.z += tv.z; r.w += tv.w;
            }
            float np = r.x * r.x + r.y * r.y + r.z * r.z + r.w * r.w;
            float n = warp_sum(np);
            float f = n / (1.f + n) * rsqrtf(n + 1e-9f);
            cap4[tid] = make_float4(r.x * f, r.y * f, r.z * f, r.w * f);
        }
        __syncthreads();

        // delta: cw[s] += hat[s,:] . cap  (unmasked)
        if (it < 2) {
            float4 cv = cap4[lane];
            for (int s2 = wid; s2 < SS; s2 += 16) {
                float4 hv = hs4[s2 * 32 + lane];
                float d = hv.x * cv.x + hv.y * cv.y + hv.z * cv.z + hv.w * cv.w;
                d = warp_sum(d);
                if (lane == 0) cw[s2] += d;
            }
            __syncthreads();
        }
    }

    if (tid < 128)
        out[(size_t)blockIdx.x * HH + tid] = capf[tid];
}

// ---------------------------------------------------------------------------
extern "C" void kernel_launch(void* const* d_in, const int* in_sizes, int n_in,
                              void* d_out, int out_size)
{
    const float* item = (const float*)d_in[0];
    const int*   mask = (const int*)d_in[1];
    const float* w    = (const float*)d_in[2];
    float*       out  = (float*)d_out;

    cudaFuncSetAttribute(gemm_hat_mma,
                         cudaFuncAttributeMaxDynamicSharedMemorySize, SMEM_GEMM);
    cudaFuncSetAttribute(routing_kernel,
                         cudaFuncAttributeMaxDynamicSharedMemorySize, SMEM_ROUTE);

    dim3 ggrid(32, SS);   // x = btile*4 + i : item shared across i, w shared across btiles
    gemm_hat_mma<<<ggrid, 256, SMEM_GEMM>>>(item, w);

    routing_kernel<<<BB * II, 512, SMEM_ROUTE>>>(mask, out);
}